// round 1
// baseline (speedup 1.0000x reference)
#include <cuda_runtime.h>

#define HH 32
#define WW 32
#define BB 16
#define NPOS 512
#define PIX 8            // pixels per block (row-contiguous, 8 | 32)
#define THREADS 256
#define SPAD 520         // smem stride per pixel (conflict-free staging writes)

// Ping-pong state scratch (no device allocation allowed).
__device__ float g_state[2][BB * HH * WW];

__device__ __forceinline__ float sigmoidf(float x) {
    return 1.0f / (1.0f + __expf(-x));
}

__global__ __launch_bounds__(THREADS, 1)
void asic_layer(const float* __restrict__ src,   // (B,H,W) previous state
                const float* __restrict__ tg,    // (NPOS,H,W) this layer's gates
                float* __restrict__ dst)         // (B,H,W)
{
    __shared__ __align__(16) float s_s[PIX][SPAD];

    const int tid = threadIdx.x;
    const int pixBase = blockIdx.x * PIX;        // flat h*W + w, all in one row

    // ---- stage + sigmoid the 8 pixels' LUT gates ----
    // idx: i = local pixel (fast, 8) -> global addresses contiguous per 8 lanes,
    // smem writes hit 8 distinct banks thanks to SPAD=520 (520 % 32 == 8).
    for (int idx = tid; idx < PIX * NPOS; idx += THREADS) {
        int p = idx >> 3;
        int i = idx & 7;
        s_s[i][p] = sigmoidf(tg[p * (HH * WW) + pixBase + i]);
    }
    __syncthreads();

    // ---- thread mapping: 2 threads per (pixel,batch) pair, split j-range ----
    const int half   = tid & 1;
    const int pairId = tid >> 1;          // 0..127
    const int batch  = pairId & (BB - 1);
    const int pixL   = pairId >> 4;       // 0..7; warp w <-> pixel w
    const int pixel  = pixBase + pixL;
    const int h = pixel >> 5;
    const int w = pixel & 31;

    // ---- gather 3x3 wrapped window: rows h+{0,1,2}, cols w+{-1,0,1} ----
    float v[9];
#pragma unroll
    for (int i0 = 0; i0 < 3; i0++) {
        int hh = h + i0; if (hh >= HH) hh -= HH;
#pragma unroll
        for (int i1 = 0; i1 < 3; i1++) {
            int ww2 = w + i1 - 1;
            if (ww2 < 0) ww2 += WW;
            if (ww2 >= WW) ww2 -= WW;
            v[i0 * 3 + i1] = src[batch * (HH * WW) + hh * WW + ww2];
        }
    }

    // ---- group partial products: bit for m is (j >> (8-m)) & 1 ----
    // a = j>>6 (m=0..2), b = (j>>3)&7 (m=3..5), c = j&7 (m=6..8)
    float PA[4], PB[8], PC[8];
#pragma unroll
    for (int q = 0; q < 8; q++) {
        PB[q] = ((q & 4) ? v[3] : 1.0f - v[3])
              * ((q & 2) ? v[4] : 1.0f - v[4])
              * ((q & 1) ? v[5] : 1.0f - v[5]);
        PC[q] = ((q & 4) ? v[6] : 1.0f - v[6])
              * ((q & 2) ? v[7] : 1.0f - v[7])
              * ((q & 1) ? v[8] : 1.0f - v[8]);
    }
#pragma unroll
    for (int a = 0; a < 4; a++) {
        int aa = half * 4 + a;
        PA[a] = ((aa & 4) ? v[0] : 1.0f - v[0])
              * ((aa & 2) ? v[1] : 1.0f - v[1])
              * ((aa & 1) ? v[2] : 1.0f - v[2]);
    }

    // ---- contraction over this half's 256 combos (vectorized smem reads) ----
    const float* sp = &s_s[pixL][half * 256];
    float acc = 0.0f;
#pragma unroll
    for (int a = 0; a < 4; a++) {
        float mid = 0.0f;
#pragma unroll
        for (int q = 0; q < 8; q++) {
            const float4* r = (const float4*)(sp + a * 64 + q * 8);
            float4 r0 = r[0];
            float4 r1 = r[1];
            float inner = ((PC[0] * r0.x + PC[1] * r0.y) + (PC[2] * r0.z + PC[3] * r0.w))
                        + ((PC[4] * r1.x + PC[5] * r1.y) + (PC[6] * r1.z + PC[7] * r1.w));
            mid = fmaf(PB[q], inner, mid);
        }
        acc = fmaf(PA[a], mid, acc);
    }

    // combine the two j-halves (adjacent lanes)
    acc += __shfl_xor_sync(0xffffffffu, acc, 1);

    if (half == 0) {
        float rres = fminf(fmaxf(acc, 0.0f), 1.0f);
        dst[batch * (HH * WW) + pixel] = rres;
    }
}

extern "C" void kernel_launch(void* const* d_in, const int* in_sizes, int n_in,
                              void* d_out, int out_size) {
    // Identify inputs by size (x: 16*32*32 = 16384, tg: 4*512*32*32 = 2097152)
    const float* x  = (const float*)d_in[0];
    const float* tg = (const float*)d_in[1];
    if (n_in >= 2 && in_sizes[0] > in_sizes[1]) {
        x  = (const float*)d_in[1];
        tg = (const float*)d_in[0];
    }
    float* out = (float*)d_out;

    float* st;
    cudaGetSymbolAddress((void**)&st, g_state);
    float* s0 = st;
    float* s1 = st + BB * HH * WW;

    const int grid = (HH * WW) / PIX;   // 128
    const int LHW = NPOS * HH * WW;     // per-layer tg stride

    asic_layer<<<grid, THREADS>>>(x,  tg + 0 * LHW, s0);
    asic_layer<<<grid, THREADS>>>(s0, tg + 1 * LHW, s1);
    asic_layer<<<grid, THREADS>>>(s1, tg + 2 * LHW, s0);
    asic_layer<<<grid, THREADS>>>(s0, tg + 3 * LHW, out);
}

// round 2
// speedup vs baseline: 1.6411x; 1.6411x over previous
#include <cuda_runtime.h>

#define HH 32
#define WW 32
#define BB 16
#define NPOS 512
#define PIX 8              // pixels per block (row-contiguous)
#define THREADS 1024
#define AROW 68            // floats per A-octant (64 data + 4 pad) -> 4-bank skew per oct
#define SROW (8 * AROW)    // 544 +4 = use 548 for per-pixel skew
#undef SROW
#define SROW 548           // floats per pixel row (8*68=544 data + 4 pad) -> 4-bank skew per pixel

// Ping-pong state scratch (no device allocation allowed).
__device__ float g_state[2][BB * HH * WW];

__device__ __forceinline__ float sigmoidf(float x) {
    // Range-safe fast sigmoid: MUFU.EX2 + MUFU.RCP, short dependency chain.
    return __fdividef(1.0f, 1.0f + __expf(-x));
}

__global__ __launch_bounds__(THREADS, 1)
void asic_layer(const float* __restrict__ src,   // (B,H,W) previous state
                const float* __restrict__ tg,    // (NPOS,H,W) this layer's gates
                float* __restrict__ dst)         // (B,H,W)
{
    __shared__ __align__(16) float s_s[PIX * SROW];

    const int tid = threadIdx.x;
    const int pixBase = blockIdx.x * PIX;        // flat h*W + w, all in one row

    // ---- stage + sigmoid the 8 pixels' LUT gates ----
    // storage: value (pixel i, combo j) at  i*SROW + (j>>6)*AROW + (j&63)
    // write banks: 4*i + 4*(j>>6) + (j&63) -> conflict-free across a warp.
#pragma unroll
    for (int it = 0; it < (PIX * NPOS) / THREADS; it++) {
        int idx = tid + it * THREADS;
        int p = idx >> 3;          // combo j
        int i = idx & 7;           // local pixel
        int a = p >> 6;
        int low = p & 63;
        s_s[i * SROW + a * AROW + low] = sigmoidf(tg[p * (HH * WW) + pixBase + i]);
    }
    __syncthreads();

    // ---- thread mapping: 8 threads per (pixel,batch) pair, one A-octant each ----
    const int oct    = tid & 7;           // A = top 3 bits of j
    const int pairId = tid >> 3;          // 0..127
    const int batch  = pairId & (BB - 1);
    const int pixL   = pairId >> 4;       // 0..7
    const int pixel  = pixBase + pixL;
    const int h = pixel >> 5;
    const int w = pixel & 31;

    // ---- gather 3x3 wrapped window: rows h+{0,1,2}, cols w+{-1,0,1} ----
    float v[9];
#pragma unroll
    for (int i0 = 0; i0 < 3; i0++) {
        int hh = h + i0; if (hh >= HH) hh -= HH;
#pragma unroll
        for (int i1 = 0; i1 < 3; i1++) {
            int ww2 = w + i1 - 1;
            if (ww2 < 0) ww2 += WW;
            if (ww2 >= WW) ww2 -= WW;
            v[i0 * 3 + i1] = src[batch * (HH * WW) + hh * WW + ww2];
        }
    }

    // ---- partial products: bit for window elem m is (j >> (8-m)) & 1 ----
    // A = j>>6 (m=0..2) -> fixed per thread (oct); B = (j>>3)&7 (m=3..5); C = j&7 (m=6..8)
    float PB[8], PC[8];
#pragma unroll
    for (int q = 0; q < 8; q++) {
        PB[q] = ((q & 4) ? v[3] : 1.0f - v[3])
              * ((q & 2) ? v[4] : 1.0f - v[4])
              * ((q & 1) ? v[5] : 1.0f - v[5]);
        PC[q] = ((q & 4) ? v[6] : 1.0f - v[6])
              * ((q & 2) ? v[7] : 1.0f - v[7])
              * ((q & 1) ? v[8] : 1.0f - v[8]);
    }
    const float PA = ((oct & 4) ? v[0] : 1.0f - v[0])
                   * ((oct & 2) ? v[1] : 1.0f - v[1])
                   * ((oct & 1) ? v[2] : 1.0f - v[2]);

    // ---- contraction over this thread's 64 combos (conflict-free LDS.128) ----
    const float* sp = s_s + pixL * SROW + oct * AROW;
    float acc0 = 0.0f, acc1 = 0.0f;
#pragma unroll
    for (int q = 0; q < 8; q += 2) {
        float4 a0 = *(const float4*)(sp + q * 8);
        float4 a1 = *(const float4*)(sp + q * 8 + 4);
        float4 b0 = *(const float4*)(sp + q * 8 + 8);
        float4 b1 = *(const float4*)(sp + q * 8 + 12);
        float innerA = ((PC[0] * a0.x + PC[1] * a0.y) + (PC[2] * a0.z + PC[3] * a0.w))
                     + ((PC[4] * a1.x + PC[5] * a1.y) + (PC[6] * a1.z + PC[7] * a1.w));
        float innerB = ((PC[0] * b0.x + PC[1] * b0.y) + (PC[2] * b0.z + PC[3] * b0.w))
                     + ((PC[4] * b1.x + PC[5] * b1.y) + (PC[6] * b1.z + PC[7] * b1.w));
        acc0 = fmaf(PB[q], innerA, acc0);
        acc1 = fmaf(PB[q + 1], innerB, acc1);
    }
    float acc = PA * (acc0 + acc1);

    // reduce over the 8 A-octant lanes
    acc += __shfl_xor_sync(0xffffffffu, acc, 1);
    acc += __shfl_xor_sync(0xffffffffu, acc, 2);
    acc += __shfl_xor_sync(0xffffffffu, acc, 4);

    if (oct == 0) {
        dst[batch * (HH * WW) + pixel] = fminf(fmaxf(acc, 0.0f), 1.0f);
    }
}

extern "C" void kernel_launch(void* const* d_in, const int* in_sizes, int n_in,
                              void* d_out, int out_size) {
    // Identify inputs by size (x: 16*32*32 = 16384, tg: 4*512*32*32 = 2097152)
    const float* x  = (const float*)d_in[0];
    const float* tg = (const float*)d_in[1];
    if (n_in >= 2 && in_sizes[0] > in_sizes[1]) {
        x  = (const float*)d_in[1];
        tg = (const float*)d_in[0];
    }
    float* out = (float*)d_out;

    float* st;
    cudaGetSymbolAddress((void**)&st, g_state);
    float* s0 = st;
    float* s1 = st + BB * HH * WW;

    const int grid = (HH * WW) / PIX;   // 128
    const int LHW = NPOS * HH * WW;     // per-layer tg stride

    asic_layer<<<grid, THREADS>>>(x,  tg + 0 * LHW, s0);
    asic_layer<<<grid, THREADS>>>(s0, tg + 1 * LHW, s1);
    asic_layer<<<grid, THREADS>>>(s1, tg + 2 * LHW, s0);
    asic_layer<<<grid, THREADS>>>(s0, tg + 3 * LHW, out);
}